// round 11
// baseline (speedup 1.0000x reference)
#include <cuda_runtime.h>
#include <cuda_bf16.h>
#include <math.h>
#include <float.h>
#include <stdint.h>

#define BB   4
#define NQ   512
#define MK   2048
#define CD   1024
#define NH   16
#define DH   64
#define BHC  (BB*NH)
#define ATTN_SCALE 0.125f

// ---------------------------------------------------------------------------
// Scratch (device globals)
// ---------------------------------------------------------------------------
__device__ __nv_bfloat16 g_Qh[(size_t)BHC * NQ * DH];
__device__ __nv_bfloat16 g_Ql[(size_t)BHC * NQ * DH];
__device__ __nv_bfloat16 g_Kh[(size_t)BHC * MK * DH];
__device__ __nv_bfloat16 g_Kl[(size_t)BHC * MK * DH];
__device__ __nv_bfloat16 g_Vh[(size_t)BHC * MK * DH];
__device__ __nv_bfloat16 g_Vl[(size_t)BHC * MK * DH];
__device__ __nv_bfloat16 g_Oh[(size_t)BB * NQ * CD];
__device__ __nv_bfloat16 g_Ol[(size_t)BB * NQ * CD];
// pre-split inputs/weights
__device__ __nv_bfloat16 g_xh[(size_t)BB * NQ * CD];
__device__ __nv_bfloat16 g_xl[(size_t)BB * NQ * CD];
__device__ __nv_bfloat16 g_ch[(size_t)BB * MK * CD];
__device__ __nv_bfloat16 g_cl[(size_t)BB * MK * CD];
__device__ __nv_bfloat16 g_wh[4][(size_t)CD * CD];
__device__ __nv_bfloat16 g_wl[4][(size_t)CD * CD];

// ---------------------------------------------------------------------------
// Helpers
// ---------------------------------------------------------------------------
__device__ __forceinline__ uint32_t smem_u32(const void* p) {
    uint32_t r;
    asm("{ .reg .u64 t; cvta.to.shared.u64 t, %1; cvt.u32.u64 %0, t; }"
        : "=r"(r) : "l"(p));
    return r;
}
__device__ __forceinline__ void ldsm4(uint32_t* r, uint32_t a) {
    asm volatile("ldmatrix.sync.aligned.m8n8.x4.shared.b16 {%0,%1,%2,%3}, [%4];"
                 : "=r"(r[0]), "=r"(r[1]), "=r"(r[2]), "=r"(r[3]) : "r"(a));
}
__device__ __forceinline__ void ldsm2(uint32_t* r, uint32_t a) {
    asm volatile("ldmatrix.sync.aligned.m8n8.x2.shared.b16 {%0,%1}, [%2];"
                 : "=r"(r[0]), "=r"(r[1]) : "r"(a));
}
__device__ __forceinline__ void ldsm2t(uint32_t* r, uint32_t a) {
    asm volatile("ldmatrix.sync.aligned.m8n8.x2.trans.shared.b16 {%0,%1}, [%2];"
                 : "=r"(r[0]), "=r"(r[1]) : "r"(a));
}
__device__ __forceinline__ void mma_bf(float* c, const uint32_t* a, const uint32_t* b) {
    asm volatile(
        "mma.sync.aligned.m16n8k16.row.col.f32.bf16.bf16.f32 "
        "{%0,%1,%2,%3}, {%4,%5,%6,%7}, {%8,%9}, {%0,%1,%2,%3};"
        : "+f"(c[0]), "+f"(c[1]), "+f"(c[2]), "+f"(c[3])
        : "r"(a[0]), "r"(a[1]), "r"(a[2]), "r"(a[3]), "r"(b[0]), "r"(b[1]));
}
__device__ __forceinline__ void split4(float4 v, uint2& h, uint2& l) {
    __nv_bfloat162 h0 = __floats2bfloat162_rn(v.x, v.y);
    __nv_bfloat162 h1 = __floats2bfloat162_rn(v.z, v.w);
    float rx = v.x - __low2float(h0);
    float ry = v.y - __high2float(h0);
    float rz = v.z - __low2float(h1);
    float rw = v.w - __high2float(h1);
    __nv_bfloat162 l0 = __floats2bfloat162_rn(rx, ry);
    __nv_bfloat162 l1 = __floats2bfloat162_rn(rz, rw);
    h.x = *reinterpret_cast<uint32_t*>(&h0);
    h.y = *reinterpret_cast<uint32_t*>(&h1);
    l.x = *reinterpret_cast<uint32_t*>(&l0);
    l.y = *reinterpret_cast<uint32_t*>(&l1);
}
__device__ __forceinline__ uint32_t packbf(float a, float b) {
    __nv_bfloat162 p = __floats2bfloat162_rn(a, b);
    return *reinterpret_cast<uint32_t*>(&p);
}
__device__ __forceinline__ void cpa(uint32_t dst, const void* src) {
    asm volatile("cp.async.cg.shared.global [%0], [%1], 16;"
                 :: "r"(dst), "l"(src) : "memory");
}
#define CPA_COMMIT() asm volatile("cp.async.commit_group;" ::: "memory")
#define CPA_WAIT2()  asm volatile("cp.async.wait_group 2;" ::: "memory")
#define CPA_WAIT1()  asm volatile("cp.async.wait_group 1;" ::: "memory")
#define CPA_WAIT0()  asm volatile("cp.async.wait_group 0;" ::: "memory")
#define SWZ(o) ((o) ^ (((o) >> 3) & 0x70))

// ---------------------------------------------------------------------------
// Kernel 0: split f32 -> bf16 hi/lo (memory-bound, one-time)
// ---------------------------------------------------------------------------
__global__ __launch_bounds__(256) void conv_split(
    const float* __restrict__ src, __nv_bfloat16* __restrict__ h,
    __nv_bfloat16* __restrict__ l, int n4)
{
    const int i = blockIdx.x * 256 + threadIdx.x;
    if (i < n4) {
        float4 v = *((const float4*)src + i);
        uint2 hh, ll;
        split4(v, hh, ll);
        *((uint2*)h + i) = hh;
        *((uint2*)l + i) = ll;
    }
}

// ---------------------------------------------------------------------------
// Kernel 1: C = A @ W^T + bias from PRE-SPLIT bf16 hi/lo operands.
// 128x128 tile, BK=32, 256 thr, 3-stage cp.async pipeline, zero split ALU.
// smem stage (32 KB): A rows [128][hi 64B | lo 64B]; W same at +16K.
// ---------------------------------------------------------------------------
#define PJ_STG 32768
#define PJ_SMEM (3 * PJ_STG)

__global__ __launch_bounds__(256) void proj_gemm_bf(
    const __nv_bfloat16* __restrict__ Ah, const __nv_bfloat16* __restrict__ Al,
    const __nv_bfloat16* __restrict__ Whi, const __nv_bfloat16* __restrict__ Wlo,
    const float* __restrict__ bias, float* __restrict__ Cf,
    __nv_bfloat16* __restrict__ Oh, __nv_bfloat16* __restrict__ Ol,
    int S, int bf16_out)
{
    extern __shared__ char sm[];
    const int tid = threadIdx.x, lane = tid & 31, wid = tid >> 5;
    const int wm = wid >> 2, wn = wid & 3;
    const int g = lane >> 2, t4 = lane & 3;
    const int rowBase = blockIdx.y * 128, colBase = blockIdx.x * 128;
    const uint32_t sb = smem_u32(sm);

    float acc[4][4][4];
#pragma unroll
    for (int i = 0; i < 4; i++)
#pragma unroll
        for (int j = 0; j < 4; j++)
#pragma unroll
            for (int k = 0; k < 4; k++) acc[i][j][k] = 0.f;

    const int tA = lane >> 3, rA = lane & 7;
    const uint32_t aRow = (uint32_t)(rA + 8 * (tA & 1));
    const uint32_t aCol = (uint32_t)((tA >> 1) * 16);
    const int rB = lane & 7, tB = (lane >> 3) & 1;

    // loader: thread t owns one row (t<128: A row t; else W row t-128), 8x16B
    const int lrow = tid & 127;
    const __nv_bfloat16* srcH = (tid < 128)
        ? Ah + (size_t)(rowBase + lrow) * CD
        : Whi + (size_t)(colBase + lrow) * CD;
    const __nv_bfloat16* srcL = (tid < 128)
        ? Al + (size_t)(rowBase + lrow) * CD
        : Wlo + (size_t)(colBase + lrow) * CD;
    const uint32_t dbase = sb + ((tid < 128) ? 0u : 16384u);

#define PJ_LOAD(stg, kt) do {                                               \
        const uint32_t s0 = dbase + (uint32_t)(stg) * PJ_STG;               \
        _Pragma("unroll")                                                   \
        for (int q = 0; q < 4; q++) {                                       \
            cpa(s0 + SWZ((uint32_t)(lrow * 128 + q * 16)),                  \
                srcH + (kt) + q * 8);                                       \
            cpa(s0 + SWZ((uint32_t)(lrow * 128 + 64 + q * 16)),             \
                srcL + (kt) + q * 8);                                       \
        }                                                                   \
        CPA_COMMIT();                                                       \
    } while (0)

    PJ_LOAD(0, 0);
    PJ_LOAD(1, 32);

    int stg = 0;
    for (int c = 0; c < 32; c++) {
        if (c + 2 < 32) {
            const int ws = (stg + 2 >= 3) ? stg - 1 : stg + 2;
            PJ_LOAD(ws, (c + 2) * 32);
        }
        if (c < 30) { CPA_WAIT2(); }
        else if (c == 30) { CPA_WAIT1(); }
        else { CPA_WAIT0(); }
        __syncthreads();

        const uint32_t sA = sb + (uint32_t)stg * PJ_STG;
        const uint32_t sB = sA + 16384;
#pragma unroll
        for (int s = 0; s < 2; s++) {
            uint32_t ah[4][4], al[4][4];
#pragma unroll
            for (int mt = 0; mt < 4; mt++) {
                const uint32_t off = (uint32_t)((wm * 64 + mt * 16 + aRow) * 128)
                                   + (uint32_t)(s * 32) + aCol;
                ldsm4(ah[mt], sA + SWZ(off));
                ldsm4(al[mt], sA + SWZ(off + 64));
            }
#pragma unroll
            for (int nt = 0; nt < 4; nt++) {
                const uint32_t boff = (uint32_t)((wn * 32 + nt * 8 + rB) * 128)
                                    + (uint32_t)(s * 32 + tB * 16);
                uint32_t bh2[2], bl2[2];
                ldsm2(bh2, sB + SWZ(boff));
                ldsm2(bl2, sB + SWZ(boff + 64));
#pragma unroll
                for (int mt = 0; mt < 4; mt++) mma_bf(acc[mt][nt], ah[mt], bh2);
#pragma unroll
                for (int mt = 0; mt < 4; mt++) mma_bf(acc[mt][nt], al[mt], bh2);
#pragma unroll
                for (int mt = 0; mt < 4; mt++) mma_bf(acc[mt][nt], ah[mt], bl2);
            }
        }
        __syncthreads();
        stg = (stg + 1 >= 3) ? 0 : stg + 1;
    }

#pragma unroll
    for (int mt = 0; mt < 4; mt++) {
        const int r0 = rowBase + wm * 64 + mt * 16 + g;
#pragma unroll
        for (int nt = 0; nt < 4; nt++) {
            const int col = colBase + wn * 32 + nt * 8 + 2 * t4;
            const float bx = bias[col], by = bias[col + 1];
            float v00 = acc[mt][nt][0] + bx, v01 = acc[mt][nt][1] + by;
            float v10 = acc[mt][nt][2] + bx, v11 = acc[mt][nt][3] + by;
            if (bf16_out) {
                const int b2 = rowBase / S;
                const int srow = r0 - b2 * S;
                const int hh = col >> 6, d = col & 63;
                const size_t base = (((size_t)(b2 * NH + hh)) * S + srow) * DH + d;
                __nv_bfloat162 h0 = __floats2bfloat162_rn(v00, v01);
                *(__nv_bfloat162*)(Oh + base) = h0;
                *(__nv_bfloat162*)(Ol + base) = __floats2bfloat162_rn(
                    v00 - __low2float(h0), v01 - __high2float(h0));
                __nv_bfloat162 h1 = __floats2bfloat162_rn(v10, v11);
                *(__nv_bfloat162*)(Oh + base + 8 * DH) = h1;
                *(__nv_bfloat162*)(Ol + base + 8 * DH) = __floats2bfloat162_rn(
                    v10 - __low2float(h1), v11 - __high2float(h1));
            } else {
                float* p0 = Cf + (size_t)r0 * CD + col;
                *(float2*)p0 = make_float2(v00, v01);
                *(float2*)(p0 + 8 * CD) = make_float2(v10, v11);
            }
        }
    }
}

// ---------------------------------------------------------------------------
// Fused flash attention (mainloop unchanged from R10; epilogue emits bf16 hi/lo)
// ---------------------------------------------------------------------------
#define OFF_Q   8192
#define OFF_ST  40960
#define ATTN_SMEM (40960 + 2 * 65536)

__global__ __launch_bounds__(256) void attn_fused(
    const __nv_bfloat16* __restrict__ Qh, const __nv_bfloat16* __restrict__ Ql,
    const __nv_bfloat16* __restrict__ Kh, const __nv_bfloat16* __restrict__ Kl,
    const __nv_bfloat16* __restrict__ Vh, const __nv_bfloat16* __restrict__ Vl,
    const int* __restrict__ mask,
    __nv_bfloat16* __restrict__ Oh, __nv_bfloat16* __restrict__ Ol)
{
    extern __shared__ char sm[];
    const int tid = threadIdx.x, lane = tid & 31, wid = tid >> 5;
    const int g = lane >> 2, t4 = lane & 3;
    const int nb = blockIdx.x, bh = blockIdx.y;
    const int b = bh >> 4, hh = bh & 15;
    const uint32_t sb = smem_u32(sm);

    const int tA = lane >> 3, rA = lane & 7;
    const uint32_t aRow = (uint32_t)(rA + 8 * (tA & 1));
    const uint32_t aCol = (uint32_t)((tA >> 1) * 16);
    const int rB = lane & 7, tB = (lane >> 3) & 1;

#pragma unroll
    for (int i = 0; i < 8; i++) {
        const int idx = tid + i * 256;
        *(float*)(sm + idx * 4) = mask[(size_t)b * MK + idx] ? 0.f : -1e30f;
    }

    const int ldrow = tid >> 3, ldc4 = tid & 7;
    {
        const size_t qb = ((size_t)bh * NQ + nb * 128) * DH;
#pragma unroll
        for (int i = 0; i < 4; i++) {
            const int row = ldrow + i * 32;
            const uint32_t so = SWZ((uint32_t)(row * 128 + ldc4 * 16));
            const size_t eo = qb + (size_t)row * DH + ldc4 * 8;
            cpa(sb + OFF_Q + so, Qh + eo);
            cpa(sb + OFF_Q + 16384 + so, Ql + eo);
        }
        const size_t kb = ((size_t)bh * MK) * DH;
        const uint32_t sk = sb + OFF_ST;
#pragma unroll
        for (int i = 0; i < 4; i++) {
            const int row = ldrow + i * 32;
            const uint32_t so = SWZ((uint32_t)(row * 128 + ldc4 * 16));
            const size_t eo = kb + (size_t)row * DH + ldc4 * 8;
            cpa(sk + so, Kh + eo);
            cpa(sk + 16384 + so, Kl + eo);
            cpa(sk + 32768 + so, Vh + eo);
            cpa(sk + 49152 + so, Vl + eo);
        }
        CPA_COMMIT();
        const size_t kb1 = ((size_t)bh * MK + 128) * DH;
        const uint32_t sk1 = sb + OFF_ST + 65536;
#pragma unroll
        for (int i = 0; i < 4; i++) {
            const int row = ldrow + i * 32;
            const uint32_t so = SWZ((uint32_t)(row * 128 + ldc4 * 16));
            const size_t eo = kb1 + (size_t)row * DH + ldc4 * 8;
            cpa(sk1 + so, Kh + eo);
            cpa(sk1 + 16384 + so, Kl + eo);
            cpa(sk1 + 32768 + so, Vh + eo);
            cpa(sk1 + 49152 + so, Vl + eo);
        }
        CPA_COMMIT();
    }

    float Oa[8][4];
#pragma unroll
    for (int i = 0; i < 8; i++)
#pragma unroll
        for (int j = 0; j < 4; j++) Oa[i][j] = 0.f;
    float rm0 = -1e30f, rm1 = -1e30f, rl0 = 0.f, rl1 = 0.f;

    for (int c = 0; c < 16; c++) {
        if (c < 15) { CPA_WAIT1(); } else { CPA_WAIT0(); }
        __syncthreads();
        const uint32_t stg = sb + OFF_ST + (c & 1) * 65536;

        float Sa[16][4];
#pragma unroll
        for (int i = 0; i < 16; i++)
#pragma unroll
            for (int j = 0; j < 4; j++) Sa[i][j] = 0.f;
#pragma unroll
        for (int s = 0; s < 4; s++) {
            uint32_t qh4[4], ql4[4];
            const uint32_t qoff = (uint32_t)((wid * 16 + aRow) * 128)
                                + (uint32_t)(s * 32) + aCol;
            ldsm4(qh4, sb + OFF_Q + SWZ(qoff));
            ldsm4(ql4, sb + OFF_Q + 16384 + SWZ(qoff));
#pragma unroll
            for (int np = 0; np < 8; np++) {
                const int n0 = 2 * np, n1 = 2 * np + 1;
                const uint32_t bo0 = (uint32_t)((n0 * 8 + rB) * 128)
                                   + (uint32_t)(s * 32 + tB * 16);
                const uint32_t bo1 = (uint32_t)((n1 * 8 + rB) * 128)
                                   + (uint32_t)(s * 32 + tB * 16);
                uint32_t kh0[2], kl0[2], kh1[2], kl1[2];
                ldsm2(kh0, stg + SWZ(bo0));
                ldsm2(kl0, stg + 16384 + SWZ(bo0));
                ldsm2(kh1, stg + SWZ(bo1));
                ldsm2(kl1, stg + 16384 + SWZ(bo1));
                mma_bf(Sa[n0], qh4, kh0);
                mma_bf(Sa[n1], qh4, kh1);
                mma_bf(Sa[n0], ql4, kh0);
                mma_bf(Sa[n1], ql4, kh1);
                mma_bf(Sa[n0], qh4, kl0);
                mma_bf(Sa[n1], qh4, kl1);
            }
        }

        float mx0 = -1e30f, mx1 = -1e30f;
#pragma unroll
        for (int nt = 0; nt < 16; nt++) {
            const int col = c * 128 + nt * 8 + 2 * t4;
            float2 bias2 = *(float2*)(sm + col * 4);
            Sa[nt][0] = Sa[nt][0] * ATTN_SCALE + bias2.x;
            Sa[nt][1] = Sa[nt][1] * ATTN_SCALE + bias2.y;
            Sa[nt][2] = Sa[nt][2] * ATTN_SCALE + bias2.x;
            Sa[nt][3] = Sa[nt][3] * ATTN_SCALE + bias2.y;
            mx0 = fmaxf(mx0, fmaxf(Sa[nt][0], Sa[nt][1]));
            mx1 = fmaxf(mx1, fmaxf(Sa[nt][2], Sa[nt][3]));
        }
        mx0 = fmaxf(mx0, __shfl_xor_sync(0xffffffffu, mx0, 1));
        mx0 = fmaxf(mx0, __shfl_xor_sync(0xffffffffu, mx0, 2));
        mx1 = fmaxf(mx1, __shfl_xor_sync(0xffffffffu, mx1, 1));
        mx1 = fmaxf(mx1, __shfl_xor_sync(0xffffffffu, mx1, 2));

        const float nm0 = fmaxf(rm0, mx0), nm1 = fmaxf(rm1, mx1);
        const float cor0 = __expf(rm0 - nm0), cor1 = __expf(rm1 - nm1);
        rm0 = nm0; rm1 = nm1;

        float sum0 = 0.f, sum1 = 0.f;
#pragma unroll
        for (int nt = 0; nt < 16; nt++) {
            Sa[nt][0] = __expf(Sa[nt][0] - nm0);
            Sa[nt][1] = __expf(Sa[nt][1] - nm0);
            Sa[nt][2] = __expf(Sa[nt][2] - nm1);
            Sa[nt][3] = __expf(Sa[nt][3] - nm1);
            sum0 += Sa[nt][0] + Sa[nt][1];
            sum1 += Sa[nt][2] + Sa[nt][3];
        }
        sum0 += __shfl_xor_sync(0xffffffffu, sum0, 1);
        sum0 += __shfl_xor_sync(0xffffffffu, sum0, 2);
        sum1 += __shfl_xor_sync(0xffffffffu, sum1, 1);
        sum1 += __shfl_xor_sync(0xffffffffu, sum1, 2);
        rl0 = rl0 * cor0 + sum0;
        rl1 = rl1 * cor1 + sum1;

#pragma unroll
        for (int i = 0; i < 8; i++) {
            Oa[i][0] *= cor0; Oa[i][1] *= cor0;
            Oa[i][2] *= cor1; Oa[i][3] *= cor1;
        }

#pragma unroll
        for (int kt = 0; kt < 8; kt++) {
            uint32_t ph[4], pl[4];
            {
                const float* pe = Sa[2 * kt];
                const float* po = Sa[2 * kt + 1];
                float h00 = __bfloat162float(__float2bfloat16(pe[0]));
                float h01 = __bfloat162float(__float2bfloat16(pe[1]));
                float h10 = __bfloat162float(__float2bfloat16(pe[2]));
                float h11 = __bfloat162float(__float2bfloat16(pe[3]));
                ph[0] = packbf(h00, h01);
                ph[1] = packbf(h10, h11);
                pl[0] = packbf(pe[0] - h00, pe[1] - h01);
                pl[1] = packbf(pe[2] - h10, pe[3] - h11);
                float o00 = __bfloat162float(__float2bfloat16(po[0]));
                float o01 = __bfloat162float(__float2bfloat16(po[1]));
                float o10 = __bfloat162float(__float2bfloat16(po[2]));
                float o11 = __bfloat162float(__float2bfloat16(po[3]));
                ph[2] = packbf(o00, o01);
                ph[3] = packbf(o10, o11);
                pl[2] = packbf(po[0] - o00, po[1] - o01);
                pl[3] = packbf(po[2] - o10, po[3] - o11);
            }
#pragma unroll
            for (int np = 0; np < 4; np++) {
                const int n0 = 2 * np, n1 = 2 * np + 1;
                const uint32_t v0 = (uint32_t)((kt * 16 + tB * 8 + rB) * 128 + n0 * 16);
                const uint32_t v1 = (uint32_t)((kt * 16 + tB * 8 + rB) * 128 + n1 * 16);
                uint32_t vh0[2], vl0[2], vh1[2], vl1[2];
                ldsm2t(vh0, stg + 32768 + SWZ(v0));
                ldsm2t(vl0, stg + 49152 + SWZ(v0));
                ldsm2t(vh1, stg + 32768 + SWZ(v1));
                ldsm2t(vl1, stg + 49152 + SWZ(v1));
                mma_bf(Oa[n0], ph, vh0);
                mma_bf(Oa[n1], ph, vh1);
                mma_bf(Oa[n0], pl, vh0);
                mma_bf(Oa[n1], pl, vh1);
                mma_bf(Oa[n0], ph, vl0);
                mma_bf(Oa[n1], ph, vl1);
            }
        }
        __syncthreads();

        if (c < 14) {
            const size_t kb = ((size_t)bh * MK + (c + 2) * 128) * DH;
            const uint32_t sk = sb + OFF_ST + (c & 1) * 65536;
#pragma unroll
            for (int i = 0; i < 4; i++) {
                const int row = ldrow + i * 32;
                const uint32_t so = SWZ((uint32_t)(row * 128 + ldc4 * 16));
                const size_t eo = kb + (size_t)row * DH + ldc4 * 8;
                cpa(sk + so, Kh + eo);
                cpa(sk + 16384 + so, Kl + eo);
                cpa(sk + 32768 + so, Vh + eo);
                cpa(sk + 49152 + so, Vl + eo);
            }
            CPA_COMMIT();
        }
    }

    // epilogue: normalize + split to bf16 hi/lo for the O projection
    const float inv0 = 1.f / rl0, inv1 = 1.f / rl1;
    const int n0 = nb * 128 + wid * 16 + g;
#pragma unroll
    for (int nt2 = 0; nt2 < 8; nt2++) {
        const int d = nt2 * 8 + 2 * t4;
        const size_t i0 = ((size_t)(b * NQ + n0)) * CD + hh * DH + d;
        float a0 = Oa[nt2][0] * inv0, a1 = Oa[nt2][1] * inv0;
        float b0 = Oa[nt2][2] * inv1, b1 = Oa[nt2][3] * inv1;
        __nv_bfloat162 h0 = __floats2bfloat162_rn(a0, a1);
        *(__nv_bfloat162*)(Oh + i0) = h0;
        *(__nv_bfloat162*)(Ol + i0) = __floats2bfloat162_rn(
            a0 - __low2float(h0), a1 - __high2float(h0));
        __nv_bfloat162 h1 = __floats2bfloat162_rn(b0, b1);
        *(__nv_bfloat162*)(Oh + i0 + 8 * CD) = h1;
        *(__nv_bfloat162*)(Ol + i0 + 8 * CD) = __floats2bfloat162_rn(
            b0 - __low2float(h1), b1 - __high2float(h1));
    }
}

// ---------------------------------------------------------------------------
// Launch
// ---------------------------------------------------------------------------
extern "C" void kernel_launch(void* const* d_in, const int* in_sizes, int n_in,
                              void* d_out, int out_size)
{
    const float* x    = (const float*)d_in[0];
    const float* ctx  = (const float*)d_in[1];
    const int*   mask = (const int*)  d_in[2];
    const float* Wq = (const float*)d_in[3];
    const float* bq = (const float*)d_in[4];
    const float* Wk = (const float*)d_in[5];
    const float* bk = (const float*)d_in[6];
    const float* Wv = (const float*)d_in[7];
    const float* bv = (const float*)d_in[8];
    const float* Wo = (const float*)d_in[9];
    const float* bo = (const float*)d_in[10];
    float* out = (float*)d_out;

    __nv_bfloat16 *pQh, *pQl, *pKh, *pKl, *pVh, *pVl, *pOh, *pOl;
    __nv_bfloat16 *pxh, *pxl, *pch, *pcl, *pwh, *pwl;
    cudaGetSymbolAddress((void**)&pQh, g_Qh);
    cudaGetSymbolAddress((void**)&pQl, g_Ql);
    cudaGetSymbolAddress((void**)&pKh, g_Kh);
    cudaGetSymbolAddress((void**)&pKl, g_Kl);
    cudaGetSymbolAddress((void**)&pVh, g_Vh);
    cudaGetSymbolAddress((void**)&pVl, g_Vl);
    cudaGetSymbolAddress((void**)&pOh, g_Oh);
    cudaGetSymbolAddress((void**)&pOl, g_Ol);
    cudaGetSymbolAddress((void**)&pxh, g_xh);
    cudaGetSymbolAddress((void**)&pxl, g_xl);
    cudaGetSymbolAddress((void**)&pch, g_ch);
    cudaGetSymbolAddress((void**)&pcl, g_cl);
    cudaGetSymbolAddress((void**)&pwh, g_wh);
    cudaGetSymbolAddress((void**)&pwl, g_wl);

    cudaFuncSetAttribute(proj_gemm_bf, cudaFuncAttributeMaxDynamicSharedMemorySize,
                         PJ_SMEM);
    cudaFuncSetAttribute(attn_fused, cudaFuncAttributeMaxDynamicSharedMemorySize,
                         ATTN_SMEM);

    const size_t WSZ = (size_t)CD * CD;
    // pre-split inputs and weights
    conv_split<<<(BB * NQ * CD / 4 + 255) / 256, 256>>>(x,   pxh, pxl, BB * NQ * CD / 4);
    conv_split<<<(BB * MK * CD / 4 + 255) / 256, 256>>>(ctx, pch, pcl, BB * MK * CD / 4);
    conv_split<<<(int)(WSZ / 4 + 255) / 256, 256>>>(Wq, pwh + 0 * WSZ, pwl + 0 * WSZ, (int)(WSZ / 4));
    conv_split<<<(int)(WSZ / 4 + 255) / 256, 256>>>(Wk, pwh + 1 * WSZ, pwl + 1 * WSZ, (int)(WSZ / 4));
    conv_split<<<(int)(WSZ / 4 + 255) / 256, 256>>>(Wv, pwh + 2 * WSZ, pwl + 2 * WSZ, (int)(WSZ / 4));
    conv_split<<<(int)(WSZ / 4 + 255) / 256, 256>>>(Wo, pwh + 3 * WSZ, pwl + 3 * WSZ, (int)(WSZ / 4));

    // projections (lean cp.async GEMM)
    proj_gemm_bf<<<dim3(8, 16), 256, PJ_SMEM>>>(pxh, pxl, pwh + 0 * WSZ, pwl + 0 * WSZ,
                                                bq, nullptr, pQh, pQl, NQ, 1);
    proj_gemm_bf<<<dim3(8, 64), 256, PJ_SMEM>>>(pch, pcl, pwh + 1 * WSZ, pwl + 1 * WSZ,
                                                bk, nullptr, pKh, pKl, MK, 1);
    proj_gemm_bf<<<dim3(8, 64), 256, PJ_SMEM>>>(pch, pcl, pwh + 2 * WSZ, pwl + 2 * WSZ,
                                                bv, nullptr, pVh, pVl, MK, 1);
    // fused attention
    attn_fused<<<dim3(4, 64), 256, ATTN_SMEM>>>(pQh, pQl, pKh, pKl, pVh, pVl,
                                                mask, pOh, pOl);
    // output projection -> d_out
    proj_gemm_bf<<<dim3(8, 16), 256, PJ_SMEM>>>(pOh, pOl, pwh + 3 * WSZ, pwl + 3 * WSZ,
                                                bo, out, nullptr, nullptr, 1, 0);
}

// round 12
// speedup vs baseline: 1.4016x; 1.4016x over previous
#include <cuda_runtime.h>
#include <cuda_bf16.h>
#include <math.h>
#include <float.h>
#include <stdint.h>

#define BB   4
#define NQ   512
#define MK   2048
#define CD   1024
#define NH   16
#define DH   64
#define BHC  (BB*NH)
#define ATTN_SCALE 0.125f

// ---------------------------------------------------------------------------
// Scratch (device globals)
// ---------------------------------------------------------------------------
__device__ __nv_bfloat16 g_Qh[(size_t)BHC * NQ * DH];
__device__ __nv_bfloat16 g_Ql[(size_t)BHC * NQ * DH];
__device__ __nv_bfloat16 g_Kh[(size_t)BHC * MK * DH];
__device__ __nv_bfloat16 g_Kl[(size_t)BHC * MK * DH];
__device__ __nv_bfloat16 g_Vh[(size_t)BHC * MK * DH];
__device__ __nv_bfloat16 g_Vl[(size_t)BHC * MK * DH];
__device__ __nv_bfloat16 g_Oh[(size_t)BB * NQ * CD];
__device__ __nv_bfloat16 g_Ol[(size_t)BB * NQ * CD];
// pre-split inputs/weights
__device__ __nv_bfloat16 g_xh[(size_t)BB * NQ * CD];
__device__ __nv_bfloat16 g_xl[(size_t)BB * NQ * CD];
__device__ __nv_bfloat16 g_ch[(size_t)BB * MK * CD];
__device__ __nv_bfloat16 g_cl[(size_t)BB * MK * CD];
__device__ __nv_bfloat16 g_wh[4][(size_t)CD * CD];
__device__ __nv_bfloat16 g_wl[4][(size_t)CD * CD];

// ---------------------------------------------------------------------------
// Helpers
// ---------------------------------------------------------------------------
__device__ __forceinline__ uint32_t smem_u32(const void* p) {
    uint32_t r;
    asm("{ .reg .u64 t; cvta.to.shared.u64 t, %1; cvt.u32.u64 %0, t; }"
        : "=r"(r) : "l"(p));
    return r;
}
__device__ __forceinline__ void ldsm4(uint32_t* r, uint32_t a) {
    asm volatile("ldmatrix.sync.aligned.m8n8.x4.shared.b16 {%0,%1,%2,%3}, [%4];"
                 : "=r"(r[0]), "=r"(r[1]), "=r"(r[2]), "=r"(r[3]) : "r"(a));
}
__device__ __forceinline__ void ldsm2(uint32_t* r, uint32_t a) {
    asm volatile("ldmatrix.sync.aligned.m8n8.x2.shared.b16 {%0,%1}, [%2];"
                 : "=r"(r[0]), "=r"(r[1]) : "r"(a));
}
__device__ __forceinline__ void ldsm2t(uint32_t* r, uint32_t a) {
    asm volatile("ldmatrix.sync.aligned.m8n8.x2.trans.shared.b16 {%0,%1}, [%2];"
                 : "=r"(r[0]), "=r"(r[1]) : "r"(a));
}
__device__ __forceinline__ void mma_bf(float* c, const uint32_t* a, const uint32_t* b) {
    asm volatile(
        "mma.sync.aligned.m16n8k16.row.col.f32.bf16.bf16.f32 "
        "{%0,%1,%2,%3}, {%4,%5,%6,%7}, {%8,%9}, {%0,%1,%2,%3};"
        : "+f"(c[0]), "+f"(c[1]), "+f"(c[2]), "+f"(c[3])
        : "r"(a[0]), "r"(a[1]), "r"(a[2]), "r"(a[3]), "r"(b[0]), "r"(b[1]));
}
__device__ __forceinline__ void split4(float4 v, uint2& h, uint2& l) {
    __nv_bfloat162 h0 = __floats2bfloat162_rn(v.x, v.y);
    __nv_bfloat162 h1 = __floats2bfloat162_rn(v.z, v.w);
    float rx = v.x - __low2float(h0);
    float ry = v.y - __high2float(h0);
    float rz = v.z - __low2float(h1);
    float rw = v.w - __high2float(h1);
    __nv_bfloat162 l0 = __floats2bfloat162_rn(rx, ry);
    __nv_bfloat162 l1 = __floats2bfloat162_rn(rz, rw);
    h.x = *reinterpret_cast<uint32_t*>(&h0);
    h.y = *reinterpret_cast<uint32_t*>(&h1);
    l.x = *reinterpret_cast<uint32_t*>(&l0);
    l.y = *reinterpret_cast<uint32_t*>(&l1);
}
__device__ __forceinline__ uint32_t packbf(float a, float b) {
    __nv_bfloat162 p = __floats2bfloat162_rn(a, b);
    return *reinterpret_cast<uint32_t*>(&p);
}
__device__ __forceinline__ void cpa(uint32_t dst, const void* src) {
    asm volatile("cp.async.cg.shared.global [%0], [%1], 16;"
                 :: "r"(dst), "l"(src) : "memory");
}
#define CPA_COMMIT() asm volatile("cp.async.commit_group;" ::: "memory")
#define CPA_WAIT2()  asm volatile("cp.async.wait_group 2;" ::: "memory")
#define CPA_WAIT1()  asm volatile("cp.async.wait_group 1;" ::: "memory")
#define CPA_WAIT0()  asm volatile("cp.async.wait_group 0;" ::: "memory")
#define SWZ(o) ((o) ^ (((o) >> 3) & 0x70))

// ---------------------------------------------------------------------------
// Kernel 0: split f32 -> bf16 hi/lo (memory-bound, one-time)
// ---------------------------------------------------------------------------
__global__ __launch_bounds__(256) void conv_split(
    const float* __restrict__ src, __nv_bfloat16* __restrict__ h,
    __nv_bfloat16* __restrict__ l, int n4)
{
    const int i = blockIdx.x * 256 + threadIdx.x;
    if (i < n4) {
        float4 v = *((const float4*)src + i);
        uint2 hh, ll;
        split4(v, hh, ll);
        *((uint2*)h + i) = hh;
        *((uint2*)l + i) = ll;
    }
}

// ---------------------------------------------------------------------------
// Kernel 1: C = A @ W^T + bias from PRE-SPLIT bf16 hi/lo operands.
// 128x128 tile, BK=32, 256 thr, 3-stage cp.async pipeline, COALESCED loader
// (warp = 8 rows x 64B contiguous segments), 2 CTAs/SM via launch bounds.
// smem stage (32 KB): A rows [128][hi 64B | lo 64B]; W same at +16K.
// ---------------------------------------------------------------------------
#define PJ_STG 32768
#define PJ_SMEM (3 * PJ_STG)

__global__ __launch_bounds__(256, 2) void proj_gemm_bf(
    const __nv_bfloat16* __restrict__ Ah, const __nv_bfloat16* __restrict__ Al,
    const __nv_bfloat16* __restrict__ Whi, const __nv_bfloat16* __restrict__ Wlo,
    const float* __restrict__ bias, float* __restrict__ Cf,
    __nv_bfloat16* __restrict__ Oh, __nv_bfloat16* __restrict__ Ol,
    int S, int bf16_out)
{
    extern __shared__ char sm[];
    const int tid = threadIdx.x, lane = tid & 31, wid = tid >> 5;
    const int wm = wid >> 2, wn = wid & 3;
    const int g = lane >> 2, t4 = lane & 3;
    const int rowBase = blockIdx.y * 128, colBase = blockIdx.x * 128;
    const uint32_t sb = smem_u32(sm);

    float acc[4][4][4];
#pragma unroll
    for (int i = 0; i < 4; i++)
#pragma unroll
        for (int j = 0; j < 4; j++)
#pragma unroll
            for (int k = 0; k < 4; k++) acc[i][j][k] = 0.f;

    const int tA = lane >> 3, rA = lane & 7;
    const uint32_t aRow = (uint32_t)(rA + 8 * (tA & 1));
    const uint32_t aCol = (uint32_t)((tA >> 1) * 16);
    const int rB = lane & 7, tB = (lane >> 3) & 1;

    // coalesced loader: thread (tid>>2) = row-quarter owner, q = tid&3
    const int lr0 = tid >> 2;       // 0..63 (rows, +64 for second half)
    const int lq  = tid & 3;        // 16B quarter within 64B half-row
    const __nv_bfloat16* Abase = Ah + (size_t)rowBase * CD;
    const __nv_bfloat16* AbaseL = Al + (size_t)rowBase * CD;
    const __nv_bfloat16* Wbase = Whi + (size_t)colBase * CD;
    const __nv_bfloat16* WbaseL = Wlo + (size_t)colBase * CD;

#define PJ_LOAD(stg, kt) do {                                               \
        const uint32_t s0 = sb + (uint32_t)(stg) * PJ_STG;                  \
        _Pragma("unroll")                                                   \
        for (int i = 0; i < 2; i++) {                                       \
            const int row = lr0 + i * 64;                                   \
            const uint32_t dh = SWZ((uint32_t)(row * 128 + lq * 16));       \
            const uint32_t dl = SWZ((uint32_t)(row * 128 + 64 + lq * 16));  \
            const size_t so = (size_t)row * CD + (kt) + lq * 8;             \
            cpa(s0 + dh, Abase + so);                                       \
            cpa(s0 + dl, AbaseL + so);                                      \
            cpa(s0 + 16384 + dh, Wbase + so);                               \
            cpa(s0 + 16384 + dl, WbaseL + so);                              \
        }                                                                   \
        CPA_COMMIT();                                                       \
    } while (0)

    PJ_LOAD(0, 0);
    PJ_LOAD(1, 32);

    int stg = 0;
    for (int c = 0; c < 32; c++) {
        if (c + 2 < 32) {
            const int ws = (stg + 2 >= 3) ? stg - 1 : stg + 2;
            PJ_LOAD(ws, (c + 2) * 32);
        }
        if (c < 30) { CPA_WAIT2(); }
        else if (c == 30) { CPA_WAIT1(); }
        else { CPA_WAIT0(); }
        __syncthreads();

        const uint32_t sA = sb + (uint32_t)stg * PJ_STG;
        const uint32_t sB = sA + 16384;
#pragma unroll
        for (int s = 0; s < 2; s++) {
            uint32_t ah[4][4], al[4][4];
#pragma unroll
            for (int mt = 0; mt < 4; mt++) {
                const uint32_t off = (uint32_t)((wm * 64 + mt * 16 + aRow) * 128)
                                   + (uint32_t)(s * 32) + aCol;
                ldsm4(ah[mt], sA + SWZ(off));
                ldsm4(al[mt], sA + SWZ(off + 64));
            }
#pragma unroll
            for (int nt = 0; nt < 4; nt++) {
                const uint32_t boff = (uint32_t)((wn * 32 + nt * 8 + rB) * 128)
                                    + (uint32_t)(s * 32 + tB * 16);
                uint32_t bh2[2], bl2[2];
                ldsm2(bh2, sB + SWZ(boff));
                ldsm2(bl2, sB + SWZ(boff + 64));
#pragma unroll
                for (int mt = 0; mt < 4; mt++) mma_bf(acc[mt][nt], ah[mt], bh2);
#pragma unroll
                for (int mt = 0; mt < 4; mt++) mma_bf(acc[mt][nt], al[mt], bh2);
#pragma unroll
                for (int mt = 0; mt < 4; mt++) mma_bf(acc[mt][nt], ah[mt], bl2);
            }
        }
        __syncthreads();
        stg = (stg + 1 >= 3) ? 0 : stg + 1;
    }

#pragma unroll
    for (int mt = 0; mt < 4; mt++) {
        const int r0 = rowBase + wm * 64 + mt * 16 + g;
#pragma unroll
        for (int nt = 0; nt < 4; nt++) {
            const int col = colBase + wn * 32 + nt * 8 + 2 * t4;
            const float bx = bias[col], by = bias[col + 1];
            float v00 = acc[mt][nt][0] + bx, v01 = acc[mt][nt][1] + by;
            float v10 = acc[mt][nt][2] + bx, v11 = acc[mt][nt][3] + by;
            if (bf16_out) {
                const int b2 = rowBase / S;
                const int srow = r0 - b2 * S;
                const int hh = col >> 6, d = col & 63;
                const size_t base = (((size_t)(b2 * NH + hh)) * S + srow) * DH + d;
                __nv_bfloat162 h0 = __floats2bfloat162_rn(v00, v01);
                *(__nv_bfloat162*)(Oh + base) = h0;
                *(__nv_bfloat162*)(Ol + base) = __floats2bfloat162_rn(
                    v00 - __low2float(h0), v01 - __high2float(h0));
                __nv_bfloat162 h1 = __floats2bfloat162_rn(v10, v11);
                *(__nv_bfloat162*)(Oh + base + 8 * DH) = h1;
                *(__nv_bfloat162*)(Ol + base + 8 * DH) = __floats2bfloat162_rn(
                    v10 - __low2float(h1), v11 - __high2float(h1));
            } else {
                float* p0 = Cf + (size_t)r0 * CD + col;
                *(float2*)p0 = make_float2(v00, v01);
                *(float2*)(p0 + 8 * CD) = make_float2(v10, v11);
            }
        }
    }
}

// ---------------------------------------------------------------------------
// Fused flash attention (unchanged mainloop; epilogue emits bf16 hi/lo)
// ---------------------------------------------------------------------------
#define OFF_Q   8192
#define OFF_ST  40960
#define ATTN_SMEM (40960 + 2 * 65536)

__global__ __launch_bounds__(256) void attn_fused(
    const __nv_bfloat16* __restrict__ Qh, const __nv_bfloat16* __restrict__ Ql,
    const __nv_bfloat16* __restrict__ Kh, const __nv_bfloat16* __restrict__ Kl,
    const __nv_bfloat16* __restrict__ Vh, const __nv_bfloat16* __restrict__ Vl,
    const int* __restrict__ mask,
    __nv_bfloat16* __restrict__ Oh, __nv_bfloat16* __restrict__ Ol)
{
    extern __shared__ char sm[];
    const int tid = threadIdx.x, lane = tid & 31, wid = tid >> 5;
    const int g = lane >> 2, t4 = lane & 3;
    const int nb = blockIdx.x, bh = blockIdx.y;
    const int b = bh >> 4, hh = bh & 15;
    const uint32_t sb = smem_u32(sm);

    const int tA = lane >> 3, rA = lane & 7;
    const uint32_t aRow = (uint32_t)(rA + 8 * (tA & 1));
    const uint32_t aCol = (uint32_t)((tA >> 1) * 16);
    const int rB = lane & 7, tB = (lane >> 3) & 1;

#pragma unroll
    for (int i = 0; i < 8; i++) {
        const int idx = tid + i * 256;
        *(float*)(sm + idx * 4) = mask[(size_t)b * MK + idx] ? 0.f : -1e30f;
    }

    const int ldrow = tid >> 3, ldc4 = tid & 7;
    {
        const size_t qb = ((size_t)bh * NQ + nb * 128) * DH;
#pragma unroll
        for (int i = 0; i < 4; i++) {
            const int row = ldrow + i * 32;
            const uint32_t so = SWZ((uint32_t)(row * 128 + ldc4 * 16));
            const size_t eo = qb + (size_t)row * DH + ldc4 * 8;
            cpa(sb + OFF_Q + so, Qh + eo);
            cpa(sb + OFF_Q + 16384 + so, Ql + eo);
        }
        const size_t kb = ((size_t)bh * MK) * DH;
        const uint32_t sk = sb + OFF_ST;
#pragma unroll
        for (int i = 0; i < 4; i++) {
            const int row = ldrow + i * 32;
            const uint32_t so = SWZ((uint32_t)(row * 128 + ldc4 * 16));
            const size_t eo = kb + (size_t)row * DH + ldc4 * 8;
            cpa(sk + so, Kh + eo);
            cpa(sk + 16384 + so, Kl + eo);
            cpa(sk + 32768 + so, Vh + eo);
            cpa(sk + 49152 + so, Vl + eo);
        }
        CPA_COMMIT();
        const size_t kb1 = ((size_t)bh * MK + 128) * DH;
        const uint32_t sk1 = sb + OFF_ST + 65536;
#pragma unroll
        for (int i = 0; i < 4; i++) {
            const int row = ldrow + i * 32;
            const uint32_t so = SWZ((uint32_t)(row * 128 + ldc4 * 16));
            const size_t eo = kb1 + (size_t)row * DH + ldc4 * 8;
            cpa(sk1 + so, Kh + eo);
            cpa(sk1 + 16384 + so, Kl + eo);
            cpa(sk1 + 32768 + so, Vh + eo);
            cpa(sk1 + 49152 + so, Vl + eo);
        }
        CPA_COMMIT();
    }

    float Oa[8][4];
#pragma unroll
    for (int i = 0; i < 8; i++)
#pragma unroll
        for (int j = 0; j < 4; j++) Oa[i][j] = 0.f;
    float rm0 = -1e30f, rm1 = -1e30f, rl0 = 0.f, rl1 = 0.f;

    for (int c = 0; c < 16; c++) {
        if (c < 15) { CPA_WAIT1(); } else { CPA_WAIT0(); }
        __syncthreads();
        const uint32_t stg = sb + OFF_ST + (c & 1) * 65536;

        float Sa[16][4];
#pragma unroll
        for (int i = 0; i < 16; i++)
#pragma unroll
            for (int j = 0; j < 4; j++) Sa[i][j] = 0.f;
#pragma unroll
        for (int s = 0; s < 4; s++) {
            uint32_t qh4[4], ql4[4];
            const uint32_t qoff = (uint32_t)((wid * 16 + aRow) * 128)
                                + (uint32_t)(s * 32) + aCol;
            ldsm4(qh4, sb + OFF_Q + SWZ(qoff));
            ldsm4(ql4, sb + OFF_Q + 16384 + SWZ(qoff));
#pragma unroll
            for (int np = 0; np < 8; np++) {
                const int n0 = 2 * np, n1 = 2 * np + 1;
                const uint32_t bo0 = (uint32_t)((n0 * 8 + rB) * 128)
                                   + (uint32_t)(s * 32 + tB * 16);
                const uint32_t bo1 = (uint32_t)((n1 * 8 + rB) * 128)
                                   + (uint32_t)(s * 32 + tB * 16);
                uint32_t kh0[2], kl0[2], kh1[2], kl1[2];
                ldsm2(kh0, stg + SWZ(bo0));
                ldsm2(kl0, stg + 16384 + SWZ(bo0));
                ldsm2(kh1, stg + SWZ(bo1));
                ldsm2(kl1, stg + 16384 + SWZ(bo1));
                mma_bf(Sa[n0], qh4, kh0);
                mma_bf(Sa[n1], qh4, kh1);
                mma_bf(Sa[n0], ql4, kh0);
                mma_bf(Sa[n1], ql4, kh1);
                mma_bf(Sa[n0], qh4, kl0);
                mma_bf(Sa[n1], qh4, kl1);
            }
        }

        float mx0 = -1e30f, mx1 = -1e30f;
#pragma unroll
        for (int nt = 0; nt < 16; nt++) {
            const int col = c * 128 + nt * 8 + 2 * t4;
            float2 bias2 = *(float2*)(sm + col * 4);
            Sa[nt][0] = Sa[nt][0] * ATTN_SCALE + bias2.x;
            Sa[nt][1] = Sa[nt][1] * ATTN_SCALE + bias2.y;
            Sa[nt][2] = Sa[nt][2] * ATTN_SCALE + bias2.x;
            Sa[nt][3] = Sa[nt][3] * ATTN_SCALE + bias2.y;
            mx0 = fmaxf(mx0, fmaxf(Sa[nt][0], Sa[nt][1]));
            mx1 = fmaxf(mx1, fmaxf(Sa[nt][2], Sa[nt][3]));
        }
        mx0 = fmaxf(mx0, __shfl_xor_sync(0xffffffffu, mx0, 1));
        mx0 = fmaxf(mx0, __shfl_xor_sync(0xffffffffu, mx0, 2));
        mx1 = fmaxf(mx1, __shfl_xor_sync(0xffffffffu, mx1, 1));
        mx1 = fmaxf(mx1, __shfl_xor_sync(0xffffffffu, mx1, 2));

        const float nm0 = fmaxf(rm0, mx0), nm1 = fmaxf(rm1, mx1);
        const float cor0 = __expf(rm0 - nm0), cor1 = __expf(rm1 - nm1);
        rm0 = nm0; rm1 = nm1;

        float sum0 = 0.f, sum1 = 0.f;
#pragma unroll
        for (int nt = 0; nt < 16; nt++) {
            Sa[nt][0] = __expf(Sa[nt][0] - nm0);
            Sa[nt][1] = __expf(Sa[nt][1] - nm0);
            Sa[nt][2] = __expf(Sa[nt][2] - nm1);
            Sa[nt][3] = __expf(Sa[nt][3] - nm1);
            sum0 += Sa[nt][0] + Sa[nt][1];
            sum1 += Sa[nt][2] + Sa[nt][3];
        }
        sum0 += __shfl_xor_sync(0xffffffffu, sum0, 1);
        sum0 += __shfl_xor_sync(0xffffffffu, sum0, 2);
        sum1 += __shfl_xor_sync(0xffffffffu, sum1, 1);
        sum1 += __shfl_xor_sync(0xffffffffu, sum1, 2);
        rl0 = rl0 * cor0 + sum0;
        rl1 = rl1 * cor1 + sum1;

#pragma unroll
        for (int i = 0; i < 8; i++) {
            Oa[i][0] *= cor0; Oa[i][1] *= cor0;
            Oa[i][2] *= cor1; Oa[i][3] *= cor1;
        }

#pragma unroll
        for (int kt = 0; kt < 8; kt++) {
            uint32_t ph[4], pl[4];
            {
                const float* pe = Sa[2 * kt];
                const float* po = Sa[2 * kt + 1];
                float h00 = __bfloat162float(__float2bfloat16(pe[0]));
                float h01 = __bfloat162float(__float2bfloat16(pe[1]));
                float h10 = __bfloat162float(__float2bfloat16(pe[2]));
                float h11 = __bfloat162float(__float2bfloat16(pe[3]));
                ph[0] = packbf(h00, h01);
                ph[1] = packbf(h10, h11);
                pl[0] = packbf(pe[0] - h00, pe[1] - h01);
                pl[1] = packbf(pe[2] - h10, pe[3] - h11);
                float o00 = __bfloat162float(__float2bfloat16(po[0]));
                float o01 = __bfloat162float(__float2bfloat16(po[1]));
                float o10 = __bfloat162float(__float2bfloat16(po[2]));
                float o11 = __bfloat162float(__float2bfloat16(po[3]));
                ph[2] = packbf(o00, o01);
                ph[3] = packbf(o10, o11);
                pl[2] = packbf(po[0] - o00, po[1] - o01);
                pl[3] = packbf(po[2] - o10, po[3] - o11);
            }
#pragma unroll
            for (int np = 0; np < 4; np++) {
                const int n0 = 2 * np, n1 = 2 * np + 1;
                const uint32_t v0 = (uint32_t)((kt * 16 + tB * 8 + rB) * 128 + n0 * 16);
                const uint32_t v1 = (uint32_t)((kt * 16 + tB * 8 + rB) * 128 + n1 * 16);
                uint32_t vh0[2], vl0[2], vh1[2], vl1[2];
                ldsm2t(vh0, stg + 32768 + SWZ(v0));
                ldsm2t(vl0, stg + 49152 + SWZ(v0));
                ldsm2t(vh1, stg + 32768 + SWZ(v1));
                ldsm2t(vl1, stg + 49152 + SWZ(v1));
                mma_bf(Oa[n0], ph, vh0);
                mma_bf(Oa[n1], ph, vh1);
                mma_bf(Oa[n0], pl, vh0);
                mma_bf(Oa[n1], pl, vh1);
                mma_bf(Oa[n0], ph, vl0);
                mma_bf(Oa[n1], ph, vl1);
            }
        }
        __syncthreads();

        if (c < 14) {
            const size_t kb = ((size_t)bh * MK + (c + 2) * 128) * DH;
            const uint32_t sk = sb + OFF_ST + (c & 1) * 65536;
#pragma unroll
            for (int i = 0; i < 4; i++) {
                const int row = ldrow + i * 32;
                const uint32_t so = SWZ((uint32_t)(row * 128 + ldc4 * 16));
                const size_t eo = kb + (size_t)row * DH + ldc4 * 8;
                cpa(sk + so, Kh + eo);
                cpa(sk + 16384 + so, Kl + eo);
                cpa(sk + 32768 + so, Vh + eo);
                cpa(sk + 49152 + so, Vl + eo);
            }
            CPA_COMMIT();
        }
    }

    const float inv0 = 1.f / rl0, inv1 = 1.f / rl1;
    const int n0 = nb * 128 + wid * 16 + g;
#pragma unroll
    for (int nt2 = 0; nt2 < 8; nt2++) {
        const int d = nt2 * 8 + 2 * t4;
        const size_t i0 = ((size_t)(b * NQ + n0)) * CD + hh * DH + d;
        float a0 = Oa[nt2][0] * inv0, a1 = Oa[nt2][1] * inv0;
        float b0 = Oa[nt2][2] * inv1, b1 = Oa[nt2][3] * inv1;
        __nv_bfloat162 h0 = __floats2bfloat162_rn(a0, a1);
        *(__nv_bfloat162*)(Oh + i0) = h0;
        *(__nv_bfloat162*)(Ol + i0) = __floats2bfloat162_rn(
            a0 - __low2float(h0), a1 - __high2float(h0));
        __nv_bfloat162 h1 = __floats2bfloat162_rn(b0, b1);
        *(__nv_bfloat162*)(Oh + i0 + 8 * CD) = h1;
        *(__nv_bfloat162*)(Ol + i0 + 8 * CD) = __floats2bfloat162_rn(
            b0 - __low2float(h1), b1 - __high2float(h1));
    }
}

// ---------------------------------------------------------------------------
// Launch
// ---------------------------------------------------------------------------
extern "C" void kernel_launch(void* const* d_in, const int* in_sizes, int n_in,
                              void* d_out, int out_size)
{
    const float* x    = (const float*)d_in[0];
    const float* ctx  = (const float*)d_in[1];
    const int*   mask = (const int*)  d_in[2];
    const float* Wq = (const float*)d_in[3];
    const float* bq = (const float*)d_in[4];
    const float* Wk = (const float*)d_in[5];
    const float* bk = (const float*)d_in[6];
    const float* Wv = (const float*)d_in[7];
    const float* bv = (const float*)d_in[8];
    const float* Wo = (const float*)d_in[9];
    const float* bo = (const float*)d_in[10];
    float* out = (float*)d_out;

    __nv_bfloat16 *pQh, *pQl, *pKh, *pKl, *pVh, *pVl, *pOh, *pOl;
    __nv_bfloat16 *pxh, *pxl, *pch, *pcl, *pwh, *pwl;
    cudaGetSymbolAddress((void**)&pQh, g_Qh);
    cudaGetSymbolAddress((void**)&pQl, g_Ql);
    cudaGetSymbolAddress((void**)&pKh, g_Kh);
    cudaGetSymbolAddress((void**)&pKl, g_Kl);
    cudaGetSymbolAddress((void**)&pVh, g_Vh);
    cudaGetSymbolAddress((void**)&pVl, g_Vl);
    cudaGetSymbolAddress((void**)&pOh, g_Oh);
    cudaGetSymbolAddress((void**)&pOl, g_Ol);
    cudaGetSymbolAddress((void**)&pxh, g_xh);
    cudaGetSymbolAddress((void**)&pxl, g_xl);
    cudaGetSymbolAddress((void**)&pch, g_ch);
    cudaGetSymbolAddress((void**)&pcl, g_cl);
    cudaGetSymbolAddress((void**)&pwh, g_wh);
    cudaGetSymbolAddress((void**)&pwl, g_wl);

    cudaFuncSetAttribute(proj_gemm_bf, cudaFuncAttributeMaxDynamicSharedMemorySize,
                         PJ_SMEM);
    cudaFuncSetAttribute(attn_fused, cudaFuncAttributeMaxDynamicSharedMemorySize,
                         ATTN_SMEM);

    const size_t WSZ = (size_t)CD * CD;
    conv_split<<<(BB * NQ * CD / 4 + 255) / 256, 256>>>(x,   pxh, pxl, BB * NQ * CD / 4);
    conv_split<<<(BB * MK * CD / 4 + 255) / 256, 256>>>(ctx, pch, pcl, BB * MK * CD / 4);
    conv_split<<<(int)(WSZ / 4 + 255) / 256, 256>>>(Wq, pwh + 0 * WSZ, pwl + 0 * WSZ, (int)(WSZ / 4));
    conv_split<<<(int)(WSZ / 4 + 255) / 256, 256>>>(Wk, pwh + 1 * WSZ, pwl + 1 * WSZ, (int)(WSZ / 4));
    conv_split<<<(int)(WSZ / 4 + 255) / 256, 256>>>(Wv, pwh + 2 * WSZ, pwl + 2 * WSZ, (int)(WSZ / 4));
    conv_split<<<(int)(WSZ / 4 + 255) / 256, 256>>>(Wo, pwh + 3 * WSZ, pwl + 3 * WSZ, (int)(WSZ / 4));

    proj_gemm_bf<<<dim3(8, 16), 256, PJ_SMEM>>>(pxh, pxl, pwh + 0 * WSZ, pwl + 0 * WSZ,
                                                bq, nullptr, pQh, pQl, NQ, 1);
    proj_gemm_bf<<<dim3(8, 64), 256, PJ_SMEM>>>(pch, pcl, pwh + 1 * WSZ, pwl + 1 * WSZ,
                                                bk, nullptr, pKh, pKl, MK, 1);
    proj_gemm_bf<<<dim3(8, 64), 256, PJ_SMEM>>>(pch, pcl, pwh + 2 * WSZ, pwl + 2 * WSZ,
                                                bv, nullptr, pVh, pVl, MK, 1);
    attn_fused<<<dim3(4, 64), 256, ATTN_SMEM>>>(pQh, pQl, pKh, pKl, pVh, pVl,
                                                mask, pOh, pOl);
    proj_gemm_bf<<<dim3(8, 16), 256, PJ_SMEM>>>(pOh, pOl, pwh + 3 * WSZ, pwl + 3 * WSZ,
                                                bo, out, nullptr, nullptr, 1, 0);
}

// round 13
// speedup vs baseline: 1.6323x; 1.1646x over previous
#include <cuda_runtime.h>
#include <cuda_bf16.h>
#include <math.h>
#include <float.h>
#include <stdint.h>

#define BB   4
#define NQ   512
#define MK   2048
#define CD   1024
#define NH   16
#define DH   64
#define BHC  (BB*NH)
#define ATTN_SCALE 0.125f

// ---------------------------------------------------------------------------
// Scratch (device globals)
// ---------------------------------------------------------------------------
__device__ __nv_bfloat16 g_Qh[(size_t)BHC * NQ * DH];
__device__ __nv_bfloat16 g_Ql[(size_t)BHC * NQ * DH];
__device__ __nv_bfloat16 g_Kh[(size_t)BHC * MK * DH];
__device__ __nv_bfloat16 g_Kl[(size_t)BHC * MK * DH];
__device__ __nv_bfloat16 g_Vh[(size_t)BHC * MK * DH];
__device__ __nv_bfloat16 g_Vl[(size_t)BHC * MK * DH];
__device__ __nv_bfloat16 g_Oh[(size_t)BB * NQ * CD];
__device__ __nv_bfloat16 g_Ol[(size_t)BB * NQ * CD];
// pre-split inputs/weights
__device__ __nv_bfloat16 g_xh[(size_t)BB * NQ * CD];
__device__ __nv_bfloat16 g_xl[(size_t)BB * NQ * CD];
__device__ __nv_bfloat16 g_ch[(size_t)BB * MK * CD];
__device__ __nv_bfloat16 g_cl[(size_t)BB * MK * CD];
__device__ __nv_bfloat16 g_wh[4][(size_t)CD * CD];
__device__ __nv_bfloat16 g_wl[4][(size_t)CD * CD];

// ---------------------------------------------------------------------------
// Helpers
// ---------------------------------------------------------------------------
__device__ __forceinline__ uint32_t smem_u32(const void* p) {
    uint32_t r;
    asm("{ .reg .u64 t; cvta.to.shared.u64 t, %1; cvt.u32.u64 %0, t; }"
        : "=r"(r) : "l"(p));
    return r;
}
__device__ __forceinline__ void ldsm4(uint32_t* r, uint32_t a) {
    asm volatile("ldmatrix.sync.aligned.m8n8.x4.shared.b16 {%0,%1,%2,%3}, [%4];"
                 : "=r"(r[0]), "=r"(r[1]), "=r"(r[2]), "=r"(r[3]) : "r"(a));
}
__device__ __forceinline__ void ldsm2(uint32_t* r, uint32_t a) {
    asm volatile("ldmatrix.sync.aligned.m8n8.x2.shared.b16 {%0,%1}, [%2];"
                 : "=r"(r[0]), "=r"(r[1]) : "r"(a));
}
__device__ __forceinline__ void ldsm2t(uint32_t* r, uint32_t a) {
    asm volatile("ldmatrix.sync.aligned.m8n8.x2.trans.shared.b16 {%0,%1}, [%2];"
                 : "=r"(r[0]), "=r"(r[1]) : "r"(a));
}
__device__ __forceinline__ void mma_bf(float* c, const uint32_t* a, const uint32_t* b) {
    asm volatile(
        "mma.sync.aligned.m16n8k16.row.col.f32.bf16.bf16.f32 "
        "{%0,%1,%2,%3}, {%4,%5,%6,%7}, {%8,%9}, {%0,%1,%2,%3};"
        : "+f"(c[0]), "+f"(c[1]), "+f"(c[2]), "+f"(c[3])
        : "r"(a[0]), "r"(a[1]), "r"(a[2]), "r"(a[3]), "r"(b[0]), "r"(b[1]));
}
__device__ __forceinline__ void split4(float4 v, uint2& h, uint2& l) {
    __nv_bfloat162 h0 = __floats2bfloat162_rn(v.x, v.y);
    __nv_bfloat162 h1 = __floats2bfloat162_rn(v.z, v.w);
    float rx = v.x - __low2float(h0);
    float ry = v.y - __high2float(h0);
    float rz = v.z - __low2float(h1);
    float rw = v.w - __high2float(h1);
    __nv_bfloat162 l0 = __floats2bfloat162_rn(rx, ry);
    __nv_bfloat162 l1 = __floats2bfloat162_rn(rz, rw);
    h.x = *reinterpret_cast<uint32_t*>(&h0);
    h.y = *reinterpret_cast<uint32_t*>(&h1);
    l.x = *reinterpret_cast<uint32_t*>(&l0);
    l.y = *reinterpret_cast<uint32_t*>(&l1);
}
__device__ __forceinline__ uint32_t packbf(float a, float b) {
    __nv_bfloat162 p = __floats2bfloat162_rn(a, b);
    return *reinterpret_cast<uint32_t*>(&p);
}
__device__ __forceinline__ void cpa(uint32_t dst, const void* src) {
    asm volatile("cp.async.cg.shared.global [%0], [%1], 16;"
                 :: "r"(dst), "l"(src) : "memory");
}
#define CPA_COMMIT() asm volatile("cp.async.commit_group;" ::: "memory")
#define CPA_WAIT2()  asm volatile("cp.async.wait_group 2;" ::: "memory")
#define CPA_WAIT1()  asm volatile("cp.async.wait_group 1;" ::: "memory")
#define CPA_WAIT0()  asm volatile("cp.async.wait_group 0;" ::: "memory")
#define SWZ(o) ((o) ^ (((o) >> 3) & 0x70))

// ---------------------------------------------------------------------------
// Kernel 0: merged split pass — all 6 tensors in ONE launch.
// Segments (float4 units): x | ctx | Wq | Wk | Wv | Wo
// ---------------------------------------------------------------------------
#define N4_X   (BB * NQ * CD / 4)              // 524288
#define N4_C   (BB * MK * CD / 4)              // 2097152
#define N4_W   (CD * CD / 4)                   // 262144
#define N4_ALL (N4_X + N4_C + 4 * N4_W)        // 3670016

__global__ __launch_bounds__(256) void conv_all(
    const float* __restrict__ x, const float* __restrict__ ctx,
    const float* __restrict__ Wq, const float* __restrict__ Wk,
    const float* __restrict__ Wv, const float* __restrict__ Wo,
    __nv_bfloat16* __restrict__ xh, __nv_bfloat16* __restrict__ xl,
    __nv_bfloat16* __restrict__ ch, __nv_bfloat16* __restrict__ cl,
    __nv_bfloat16* __restrict__ wh, __nv_bfloat16* __restrict__ wl)
{
    int i = blockIdx.x * 256 + threadIdx.x;
    if (i >= N4_ALL) return;
    const float* src;
    __nv_bfloat16 *dh, *dl;
    if (i < N4_X) {
        src = x; dh = xh; dl = xl;
    } else if (i < N4_X + N4_C) {
        i -= N4_X; src = ctx; dh = ch; dl = cl;
    } else {
        int t = i - N4_X - N4_C;
        const int w = t / N4_W;
        i = t - w * N4_W;
        src = (w == 0) ? Wq : (w == 1) ? Wk : (w == 2) ? Wv : Wo;
        dh = wh + (size_t)w * (CD * CD);
        dl = wl + (size_t)w * (CD * CD);
    }
    float4 v = *((const float4*)src + i);
    uint2 hh, ll;
    split4(v, hh, ll);
    *((uint2*)dh + i) = hh;
    *((uint2*)dl + i) = ll;
}

// ---------------------------------------------------------------------------
// Shared projection body: C = A @ W^T + bias from pre-split bf16 hi/lo.
// 128x128 tile, BK=32, 256 thr, 3-stage cp.async, coalesced loader.
// ---------------------------------------------------------------------------
#define PJ_STG 32768
#define PJ_SMEM (3 * PJ_STG)

__device__ __forceinline__ void proj_body(
    char* sm,
    const __nv_bfloat16* __restrict__ Ah, const __nv_bfloat16* __restrict__ Al,
    const __nv_bfloat16* __restrict__ Whi, const __nv_bfloat16* __restrict__ Wlo,
    const float* __restrict__ bias, float* __restrict__ Cf,
    __nv_bfloat16* __restrict__ Oh, __nv_bfloat16* __restrict__ Ol,
    int rowBase, int colBase, int S, int bf16_out)
{
    const int tid = threadIdx.x, lane = tid & 31, wid = tid >> 5;
    const int wm = wid >> 2, wn = wid & 3;
    const int g = lane >> 2, t4 = lane & 3;
    const uint32_t sb = smem_u32(sm);

    float acc[4][4][4];
#pragma unroll
    for (int i = 0; i < 4; i++)
#pragma unroll
        for (int j = 0; j < 4; j++)
#pragma unroll
            for (int k = 0; k < 4; k++) acc[i][j][k] = 0.f;

    const int tA = lane >> 3, rA = lane & 7;
    const uint32_t aRow = (uint32_t)(rA + 8 * (tA & 1));
    const uint32_t aCol = (uint32_t)((tA >> 1) * 16);
    const int rB = lane & 7, tB = (lane >> 3) & 1;

    const int lr0 = tid >> 2;
    const int lq  = tid & 3;
    const __nv_bfloat16* Abase  = Ah  + (size_t)rowBase * CD;
    const __nv_bfloat16* AbaseL = Al  + (size_t)rowBase * CD;
    const __nv_bfloat16* Wbase  = Whi + (size_t)colBase * CD;
    const __nv_bfloat16* WbaseL = Wlo + (size_t)colBase * CD;

#define PJ_LOAD(stg, kt) do {                                               \
        const uint32_t s0 = sb + (uint32_t)(stg) * PJ_STG;                  \
        _Pragma("unroll")                                                   \
        for (int i = 0; i < 2; i++) {                                       \
            const int row = lr0 + i * 64;                                   \
            const uint32_t dh = SWZ((uint32_t)(row * 128 + lq * 16));       \
            const uint32_t dl = SWZ((uint32_t)(row * 128 + 64 + lq * 16));  \
            const size_t so = (size_t)row * CD + (kt) + lq * 8;             \
            cpa(s0 + dh, Abase + so);                                       \
            cpa(s0 + dl, AbaseL + so);                                      \
            cpa(s0 + 16384 + dh, Wbase + so);                               \
            cpa(s0 + 16384 + dl, WbaseL + so);                              \
        }                                                                   \
        CPA_COMMIT();                                                       \
    } while (0)

    PJ_LOAD(0, 0);
    PJ_LOAD(1, 32);

    int stg = 0;
    for (int c = 0; c < 32; c++) {
        if (c + 2 < 32) {
            const int ws = (stg + 2 >= 3) ? stg - 1 : stg + 2;
            PJ_LOAD(ws, (c + 2) * 32);
        }
        if (c < 30) { CPA_WAIT2(); }
        else if (c == 30) { CPA_WAIT1(); }
        else { CPA_WAIT0(); }
        __syncthreads();

        const uint32_t sA = sb + (uint32_t)stg * PJ_STG;
        const uint32_t sB = sA + 16384;
#pragma unroll
        for (int s = 0; s < 2; s++) {
            uint32_t ah[4][4], al[4][4];
#pragma unroll
            for (int mt = 0; mt < 4; mt++) {
                const uint32_t off = (uint32_t)((wm * 64 + mt * 16 + aRow) * 128)
                                   + (uint32_t)(s * 32) + aCol;
                ldsm4(ah[mt], sA + SWZ(off));
                ldsm4(al[mt], sA + SWZ(off + 64));
            }
#pragma unroll
            for (int nt = 0; nt < 4; nt++) {
                const uint32_t boff = (uint32_t)((wn * 32 + nt * 8 + rB) * 128)
                                    + (uint32_t)(s * 32 + tB * 16);
                uint32_t bh2[2], bl2[2];
                ldsm2(bh2, sB + SWZ(boff));
                ldsm2(bl2, sB + SWZ(boff + 64));
#pragma unroll
                for (int mt = 0; mt < 4; mt++) mma_bf(acc[mt][nt], ah[mt], bh2);
#pragma unroll
                for (int mt = 0; mt < 4; mt++) mma_bf(acc[mt][nt], al[mt], bh2);
#pragma unroll
                for (int mt = 0; mt < 4; mt++) mma_bf(acc[mt][nt], ah[mt], bl2);
            }
        }
        __syncthreads();
        stg = (stg + 1 >= 3) ? 0 : stg + 1;
    }

#pragma unroll
    for (int mt = 0; mt < 4; mt++) {
        const int r0 = rowBase + wm * 64 + mt * 16 + g;
#pragma unroll
        for (int nt = 0; nt < 4; nt++) {
            const int col = colBase + wn * 32 + nt * 8 + 2 * t4;
            const float bx = bias[col], by = bias[col + 1];
            float v00 = acc[mt][nt][0] + bx, v01 = acc[mt][nt][1] + by;
            float v10 = acc[mt][nt][2] + bx, v11 = acc[mt][nt][3] + by;
            if (bf16_out) {
                const int b2 = rowBase / S;
                const int srow = r0 - b2 * S;
                const int hh = col >> 6, d = col & 63;
                const size_t base = (((size_t)(b2 * NH + hh)) * S + srow) * DH + d;
                __nv_bfloat162 h0 = __floats2bfloat162_rn(v00, v01);
                *(__nv_bfloat162*)(Oh + base) = h0;
                *(__nv_bfloat162*)(Ol + base) = __floats2bfloat162_rn(
                    v00 - __low2float(h0), v01 - __high2float(h0));
                __nv_bfloat162 h1 = __floats2bfloat162_rn(v10, v11);
                *(__nv_bfloat162*)(Oh + base + 8 * DH) = h1;
                *(__nv_bfloat162*)(Ol + base + 8 * DH) = __floats2bfloat162_rn(
                    v10 - __low2float(h1), v11 - __high2float(h1));
            } else {
                float* p0 = Cf + (size_t)r0 * CD + col;
                *(float2*)p0 = make_float2(v00, v01);
                *(float2*)(p0 + 8 * CD) = make_float2(v10, v11);
            }
        }
    }
#undef PJ_LOAD
}

// ---------------------------------------------------------------------------
// Mega QKV projection: ONE launch, 1152 CTAs.
//   bid [0,128)   : Q  = x   @ Wq^T  (grid 8x16)
//   bid [128,640) : K  = ctx @ Wk^T  (grid 8x64)
//   bid [640,1152): V  = ctx @ Wv^T  (grid 8x64)
// ---------------------------------------------------------------------------
__global__ __launch_bounds__(256, 2) void qkv_mega(
    const __nv_bfloat16* __restrict__ xh, const __nv_bfloat16* __restrict__ xl,
    const __nv_bfloat16* __restrict__ ch, const __nv_bfloat16* __restrict__ cl,
    const __nv_bfloat16* __restrict__ wh, const __nv_bfloat16* __restrict__ wl,
    const float* __restrict__ bq, const float* __restrict__ bk,
    const float* __restrict__ bv,
    __nv_bfloat16* __restrict__ Qh, __nv_bfloat16* __restrict__ Ql,
    __nv_bfloat16* __restrict__ Kh, __nv_bfloat16* __restrict__ Kl,
    __nv_bfloat16* __restrict__ Vh, __nv_bfloat16* __restrict__ Vl)
{
    extern __shared__ char sm[];
    const int bid = blockIdx.x;
    const size_t WSZ = (size_t)CD * CD;

    const __nv_bfloat16 *Ah, *Al, *Whi, *Wlo;
    const float* bias;
    __nv_bfloat16 *Oh, *Ol;
    int t, S;
    if (bid < 128) {
        t = bid; S = NQ;
        Ah = xh; Al = xl; Whi = wh; Wlo = wl;
        bias = bq; Oh = Qh; Ol = Ql;
    } else if (bid < 640) {
        t = bid - 128; S = MK;
        Ah = ch; Al = cl; Whi = wh + WSZ; Wlo = wl + WSZ;
        bias = bk; Oh = Kh; Ol = Kl;
    } else {
        t = bid - 640; S = MK;
        Ah = ch; Al = cl; Whi = wh + 2 * WSZ; Wlo = wl + 2 * WSZ;
        bias = bv; Oh = Vh; Ol = Vl;
    }
    const int rowBase = (t >> 3) * 128;
    const int colBase = (t & 7) * 128;
    proj_body(sm, Ah, Al, Whi, Wlo, bias, nullptr, Oh, Ol,
              rowBase, colBase, S, 1);
}

// O projection (separate: depends on attention output)
__global__ __launch_bounds__(256, 2) void proj_o(
    const __nv_bfloat16* __restrict__ Ah, const __nv_bfloat16* __restrict__ Al,
    const __nv_bfloat16* __restrict__ Whi, const __nv_bfloat16* __restrict__ Wlo,
    const float* __restrict__ bias, float* __restrict__ Cf)
{
    extern __shared__ char sm[];
    proj_body(sm, Ah, Al, Whi, Wlo, bias, Cf, nullptr, nullptr,
              blockIdx.y * 128, blockIdx.x * 128, 1, 0);
}

// ---------------------------------------------------------------------------
// Fused flash attention (byte-identical mainloop to R12)
// ---------------------------------------------------------------------------
#define OFF_Q   8192
#define OFF_ST  40960
#define ATTN_SMEM (40960 + 2 * 65536)

__global__ __launch_bounds__(256) void attn_fused(
    const __nv_bfloat16* __restrict__ Qh, const __nv_bfloat16* __restrict__ Ql,
    const __nv_bfloat16* __restrict__ Kh, const __nv_bfloat16* __restrict__ Kl,
    const __nv_bfloat16* __restrict__ Vh, const __nv_bfloat16* __restrict__ Vl,
    const int* __restrict__ mask,
    __nv_bfloat16* __restrict__ Oh, __nv_bfloat16* __restrict__ Ol)
{
    extern __shared__ char sm[];
    const int tid = threadIdx.x, lane = tid & 31, wid = tid >> 5;
    const int g = lane >> 2, t4 = lane & 3;
    const int nb = blockIdx.x, bh = blockIdx.y;
    const int b = bh >> 4, hh = bh & 15;
    const uint32_t sb = smem_u32(sm);

    const int tA = lane >> 3, rA = lane & 7;
    const uint32_t aRow = (uint32_t)(rA + 8 * (tA & 1));
    const uint32_t aCol = (uint32_t)((tA >> 1) * 16);
    const int rB = lane & 7, tB = (lane >> 3) & 1;

#pragma unroll
    for (int i = 0; i < 8; i++) {
        const int idx = tid + i * 256;
        *(float*)(sm + idx * 4) = mask[(size_t)b * MK + idx] ? 0.f : -1e30f;
    }

    const int ldrow = tid >> 3, ldc4 = tid & 7;
    {
        const size_t qb = ((size_t)bh * NQ + nb * 128) * DH;
#pragma unroll
        for (int i = 0; i < 4; i++) {
            const int row = ldrow + i * 32;
            const uint32_t so = SWZ((uint32_t)(row * 128 + ldc4 * 16));
            const size_t eo = qb + (size_t)row * DH + ldc4 * 8;
            cpa(sb + OFF_Q + so, Qh + eo);
            cpa(sb + OFF_Q + 16384 + so, Ql + eo);
        }
        const size_t kb = ((size_t)bh * MK) * DH;
        const uint32_t sk = sb + OFF_ST;
#pragma unroll
        for (int i = 0; i < 4; i++) {
            const int row = ldrow + i * 32;
            const uint32_t so = SWZ((uint32_t)(row * 128 + ldc4 * 16));
            const size_t eo = kb + (size_t)row * DH + ldc4 * 8;
            cpa(sk + so, Kh + eo);
            cpa(sk + 16384 + so, Kl + eo);
            cpa(sk + 32768 + so, Vh + eo);
            cpa(sk + 49152 + so, Vl + eo);
        }
        CPA_COMMIT();
        const size_t kb1 = ((size_t)bh * MK + 128) * DH;
        const uint32_t sk1 = sb + OFF_ST + 65536;
#pragma unroll
        for (int i = 0; i < 4; i++) {
            const int row = ldrow + i * 32;
            const uint32_t so = SWZ((uint32_t)(row * 128 + ldc4 * 16));
            const size_t eo = kb1 + (size_t)row * DH + ldc4 * 8;
            cpa(sk1 + so, Kh + eo);
            cpa(sk1 + 16384 + so, Kl + eo);
            cpa(sk1 + 32768 + so, Vh + eo);
            cpa(sk1 + 49152 + so, Vl + eo);
        }
        CPA_COMMIT();
    }

    float Oa[8][4];
#pragma unroll
    for (int i = 0; i < 8; i++)
#pragma unroll
        for (int j = 0; j < 4; j++) Oa[i][j] = 0.f;
    float rm0 = -1e30f, rm1 = -1e30f, rl0 = 0.f, rl1 = 0.f;

    for (int c = 0; c < 16; c++) {
        if (c < 15) { CPA_WAIT1(); } else { CPA_WAIT0(); }
        __syncthreads();
        const uint32_t stg = sb + OFF_ST + (c & 1) * 65536;

        float Sa[16][4];
#pragma unroll
        for (int i = 0; i < 16; i++)
#pragma unroll
            for (int j = 0; j < 4; j++) Sa[i][j] = 0.f;
#pragma unroll
        for (int s = 0; s < 4; s++) {
            uint32_t qh4[4], ql4[4];
            const uint32_t qoff = (uint32_t)((wid * 16 + aRow) * 128)
                                + (uint32_t)(s * 32) + aCol;
            ldsm4(qh4, sb + OFF_Q + SWZ(qoff));
            ldsm4(ql4, sb + OFF_Q + 16384 + SWZ(qoff));
#pragma unroll
            for (int np = 0; np < 8; np++) {
                const int n0 = 2 * np, n1 = 2 * np + 1;
                const uint32_t bo0 = (uint32_t)((n0 * 8 + rB) * 128)
                                   + (uint32_t)(s * 32 + tB * 16);
                const uint32_t bo1 = (uint32_t)((n1 * 8 + rB) * 128)
                                   + (uint32_t)(s * 32 + tB * 16);
                uint32_t kh0[2], kl0[2], kh1[2], kl1[2];
                ldsm2(kh0, stg + SWZ(bo0));
                ldsm2(kl0, stg + 16384 + SWZ(bo0));
                ldsm2(kh1, stg + SWZ(bo1));
                ldsm2(kl1, stg + 16384 + SWZ(bo1));
                mma_bf(Sa[n0], qh4, kh0);
                mma_bf(Sa[n1], qh4, kh1);
                mma_bf(Sa[n0], ql4, kh0);
                mma_bf(Sa[n1], ql4, kh1);
                mma_bf(Sa[n0], qh4, kl0);
                mma_bf(Sa[n1], qh4, kl1);
            }
        }

        float mx0 = -1e30f, mx1 = -1e30f;
#pragma unroll
        for (int nt = 0; nt < 16; nt++) {
            const int col = c * 128 + nt * 8 + 2 * t4;
            float2 bias2 = *(float2*)(sm + col * 4);
            Sa[nt][0] = Sa[nt][0] * ATTN_SCALE + bias2.x;
            Sa[nt][1] = Sa[nt][1] * ATTN_SCALE + bias2.y;
            Sa[nt][2] = Sa[nt][2] * ATTN_SCALE + bias2.x;
            Sa[nt][3] = Sa[nt][3] * ATTN_SCALE + bias2.y;
            mx0 = fmaxf(mx0, fmaxf(Sa[nt][0], Sa[nt][1]));
            mx1 = fmaxf(mx1, fmaxf(Sa[nt][2], Sa[nt][3]));
        }
        mx0 = fmaxf(mx0, __shfl_xor_sync(0xffffffffu, mx0, 1));
        mx0 = fmaxf(mx0, __shfl_xor_sync(0xffffffffu, mx0, 2));
        mx1 = fmaxf(mx1, __shfl_xor_sync(0xffffffffu, mx1, 1));
        mx1 = fmaxf(mx1, __shfl_xor_sync(0xffffffffu, mx1, 2));

        const float nm0 = fmaxf(rm0, mx0), nm1 = fmaxf(rm1, mx1);
        const float cor0 = __expf(rm0 - nm0), cor1 = __expf(rm1 - nm1);
        rm0 = nm0; rm1 = nm1;

        float sum0 = 0.f, sum1 = 0.f;
#pragma unroll
        for (int nt = 0; nt < 16; nt++) {
            Sa[nt][0] = __expf(Sa[nt][0] - nm0);
            Sa[nt][1] = __expf(Sa[nt][1] - nm0);
            Sa[nt][2] = __expf(Sa[nt][2] - nm1);
            Sa[nt][3] = __expf(Sa[nt][3] - nm1);
            sum0 += Sa[nt][0] + Sa[nt][1];
            sum1 += Sa[nt][2] + Sa[nt][3];
        }
        sum0 += __shfl_xor_sync(0xffffffffu, sum0, 1);
        sum0 += __shfl_xor_sync(0xffffffffu, sum0, 2);
        sum1 += __shfl_xor_sync(0xffffffffu, sum1, 1);
        sum1 += __shfl_xor_sync(0xffffffffu, sum1, 2);
        rl0 = rl0 * cor0 + sum0;
        rl1 = rl1 * cor1 + sum1;

#pragma unroll
        for (int i = 0; i < 8; i++) {
            Oa[i][0] *= cor0; Oa[i][1] *= cor0;
            Oa[i][2] *= cor1; Oa[i][3] *= cor1;
        }

#pragma unroll
        for (int kt = 0; kt < 8; kt++) {
            uint32_t ph[4], pl[4];
            {
                const float* pe = Sa[2 * kt];
                const float* po = Sa[2 * kt + 1];
                float h00 = __bfloat162float(__float2bfloat16(pe[0]));
                float h01 = __bfloat162float(__float2bfloat16(pe[1]));
                float h10 = __bfloat162float(__float2bfloat16(pe[2]));
                float h11 = __bfloat162float(__float2bfloat16(pe[3]));
                ph[0] = packbf(h00, h01);
                ph[1] = packbf(h10, h11);
                pl[0] = packbf(pe[0] - h00, pe[1] - h01);
                pl[1] = packbf(pe[2] - h10, pe[3] - h11);
                float o00 = __bfloat162float(__float2bfloat16(po[0]));
                float o01 = __bfloat162float(__float2bfloat16(po[1]));
                float o10 = __bfloat162float(__float2bfloat16(po[2]));
                float o11 = __bfloat162float(__float2bfloat16(po[3]));
                ph[2] = packbf(o00, o01);
                ph[3] = packbf(o10, o11);
                pl[2] = packbf(po[0] - o00, po[1] - o01);
                pl[3] = packbf(po[2] - o10, po[3] - o11);
            }
#pragma unroll
            for (int np = 0; np < 4; np++) {
                const int n0 = 2 * np, n1 = 2 * np + 1;
                const uint32_t v0 = (uint32_t)((kt * 16 + tB * 8 + rB) * 128 + n0 * 16);
                const uint32_t v1 = (uint32_t)((kt * 16 + tB * 8 + rB) * 128 + n1 * 16);
                uint32_t vh0[2], vl0[2], vh1[2], vl1[2];
                ldsm2t(vh0, stg + 32768 + SWZ(v0));
                ldsm2t(vl0, stg + 49152 + SWZ(v0));
                ldsm2t(vh1, stg + 32768 + SWZ(v1));
                ldsm2t(vl1, stg + 49152 + SWZ(v1));
                mma_bf(Oa[n0], ph, vh0);
                mma_bf(Oa[n1], ph, vh1);
                mma_bf(Oa[n0], pl, vh0);
                mma_bf(Oa[n1], pl, vh1);
                mma_bf(Oa[n0], ph, vl0);
                mma_bf(Oa[n1], ph, vl1);
            }
        }
        __syncthreads();

        if (c < 14) {
            const size_t kb = ((size_t)bh * MK + (c + 2) * 128) * DH;
            const uint32_t sk = sb + OFF_ST + (c & 1) * 65536;
#pragma unroll
            for (int i = 0; i < 4; i++) {
                const int row = ldrow + i * 32;
                const uint32_t so = SWZ((uint32_t)(row * 128 + ldc4 * 16));
                const size_t eo = kb + (size_t)row * DH + ldc4 * 8;
                cpa(sk + so, Kh + eo);
                cpa(sk + 16384 + so, Kl + eo);
                cpa(sk + 32768 + so, Vh + eo);
                cpa(sk + 49152 + so, Vl + eo);
            }
            CPA_COMMIT();
        }
    }

    const float inv0 = 1.f / rl0, inv1 = 1.f / rl1;
    const int n0 = nb * 128 + wid * 16 + g;
#pragma unroll
    for (int nt2 = 0; nt2 < 8; nt2++) {
        const int d = nt2 * 8 + 2 * t4;
        const size_t i0 = ((size_t)(b * NQ + n0)) * CD + hh * DH + d;
        float a0 = Oa[nt2][0] * inv0, a1 = Oa[nt2][1] * inv0;
        float b0 = Oa[nt2][2] * inv1, b1 = Oa[nt2][3] * inv1;
        __nv_bfloat162 h0 = __floats2bfloat162_rn(a0, a1);
        *(__nv_bfloat162*)(Oh + i0) = h0;
        *(__nv_bfloat162*)(Ol + i0) = __floats2bfloat162_rn(
            a0 - __low2float(h0), a1 - __high2float(h0));
        __nv_bfloat162 h1 = __floats2bfloat162_rn(b0, b1);
        *(__nv_bfloat162*)(Oh + i0 + 8 * CD) = h1;
        *(__nv_bfloat162*)(Ol + i0 + 8 * CD) = __floats2bfloat162_rn(
            b0 - __low2float(h1), b1 - __high2float(h1));
    }
}

// ---------------------------------------------------------------------------
// Launch
// ---------------------------------------------------------------------------
extern "C" void kernel_launch(void* const* d_in, const int* in_sizes, int n_in,
                              void* d_out, int out_size)
{
    const float* x    = (const float*)d_in[0];
    const float* ctx  = (const float*)d_in[1];
    const int*   mask = (const int*)  d_in[2];
    const float* Wq = (const float*)d_in[3];
    const float* bq = (const float*)d_in[4];
    const float* Wk = (const float*)d_in[5];
    const float* bk = (const float*)d_in[6];
    const float* Wv = (const float*)d_in[7];
    const float* bv = (const float*)d_in[8];
    const float* Wo = (const float*)d_in[9];
    const float* bo = (const float*)d_in[10];
    float* out = (float*)d_out;

    __nv_bfloat16 *pQh, *pQl, *pKh, *pKl, *pVh, *pVl, *pOh, *pOl;
    __nv_bfloat16 *pxh, *pxl, *pch, *pcl, *pwh, *pwl;
    cudaGetSymbolAddress((void**)&pQh, g_Qh);
    cudaGetSymbolAddress((void**)&pQl, g_Ql);
    cudaGetSymbolAddress((void**)&pKh, g_Kh);
    cudaGetSymbolAddress((void**)&pKl, g_Kl);
    cudaGetSymbolAddress((void**)&pVh, g_Vh);
    cudaGetSymbolAddress((void**)&pVl, g_Vl);
    cudaGetSymbolAddress((void**)&pOh, g_Oh);
    cudaGetSymbolAddress((void**)&pOl, g_Ol);
    cudaGetSymbolAddress((void**)&pxh, g_xh);
    cudaGetSymbolAddress((void**)&pxl, g_xl);
    cudaGetSymbolAddress((void**)&pch, g_ch);
    cudaGetSymbolAddress((void**)&pcl, g_cl);
    cudaGetSymbolAddress((void**)&pwh, g_wh);
    cudaGetSymbolAddress((void**)&pwl, g_wl);

    cudaFuncSetAttribute(qkv_mega, cudaFuncAttributeMaxDynamicSharedMemorySize,
                         PJ_SMEM);
    cudaFuncSetAttribute(proj_o, cudaFuncAttributeMaxDynamicSharedMemorySize,
                         PJ_SMEM);
    cudaFuncSetAttribute(attn_fused, cudaFuncAttributeMaxDynamicSharedMemorySize,
                         ATTN_SMEM);

    const size_t WSZ = (size_t)CD * CD;
    // one-shot split of inputs + all weights (single launch)
    conv_all<<<(N4_ALL + 255) / 256, 256>>>(x, ctx, Wq, Wk, Wv, Wo,
                                            pxh, pxl, pch, pcl, pwh, pwl);
    // Q,K,V projections fused into one launch (1152 CTAs)
    qkv_mega<<<1152, 256, PJ_SMEM>>>(pxh, pxl, pch, pcl, pwh, pwl,
                                     bq, bk, bv,
                                     pQh, pQl, pKh, pKl, pVh, pVl);
    // fused attention
    attn_fused<<<dim3(4, 64), 256, ATTN_SMEM>>>(pQh, pQl, pKh, pKl, pVh, pVl,
                                                mask, pOh, pOl);
    // output projection -> d_out
    proj_o<<<dim3(8, 16), 256, PJ_SMEM>>>(pOh, pOl, pwh + 3 * WSZ, pwl + 3 * WSZ,
                                          bo, out);
}